// round 15
// baseline (speedup 1.0000x reference)
#include <cuda_runtime.h>
#include <cuda_bf16.h>
#include <cuda_fp16.h>
#include <cstdint>

#define NN   10000
#define EE   160000
#define DIN  128
#define HH   1024
#define GG   8
#define HV   (HH/4)   // 256 float4 per row
#define EPSL 1e-5f

// ---------------- device scratch (static; no allocation allowed) ----------------
__device__ float g_dinv[NN];
__device__ int   g_cnt[NN];
__device__ int   g_off[NN + 1];
__device__ int   g_cur[NN];
__device__ int   g_csr[EE];
__device__ __half g_hw[(size_t)NN * HH]; // (A@W) * dinv[row], fp16 (agg-only operand)
__device__ float g_x1[(size_t)NN * HH];   // saved x1 for residuals (fp32)
__device__ float g_h [(size_t)NN * HH];   // current activation (fp32)
__device__ float g_pool[GG * HH];
__device__ int   g_start[GG + 1];
__device__ float g_vbuf[2][GG * HH];
__device__ float g_mpart[8][GG * HH];     // MLP k-split partials
// fp16 operand buffers for tensor-core GEMMs (A single fp16; W split hi/lo fp16)
__device__ __half g_a16[(size_t)NN * HH];      // activations, fp16
__device__ __half g_x16[(size_t)NN * DIN];     // input x, fp16
__device__ __half g_wthi[3 * (size_t)HH * HH]; // Wh transposed [N,K], fp16 hi
__device__ __half g_wtlo[3 * (size_t)HH * HH]; // fp16 lo
__device__ __half g_w1thi[(size_t)HH * DIN];   // W1 transposed [1024,128]
__device__ __half g_w1tlo[(size_t)HH * DIN];

// ---------------- degree / CSR construction ----------------
__global__ void k_count_deg(const int* __restrict__ dst) {
    int e = blockIdx.x * blockDim.x + threadIdx.x;
    if (e < EE) atomicAdd(&g_cnt[dst[e]], 1);
}

__global__ void k_fin_dinv() {
    int i = blockIdx.x * blockDim.x + threadIdx.x;
    if (i < NN) {
        float deg = (float)(g_cnt[i] + 1);
        g_dinv[i] = rsqrtf(deg);
        g_cur[i]  = 0;
    }
}

__global__ void k_scan_off() {
    __shared__ int partial[1024];
    int t = threadIdx.x;
    int base = t * 10;
    int local[10];
    int s = 0;
    if (t < 1000) {
        #pragma unroll
        for (int j = 0; j < 10; j++) { local[j] = s; s += g_cnt[base + j]; }
    }
    partial[t] = (t < 1000) ? s : 0;
    __syncthreads();
    for (int d = 1; d < 1024; d <<= 1) {
        int v = partial[t];
        int add = (t >= d) ? partial[t - d] : 0;
        __syncthreads();
        partial[t] = v + add;
        __syncthreads();
    }
    int pre = (t > 0) ? partial[t - 1] : 0;
    if (t < 1000) {
        #pragma unroll
        for (int j = 0; j < 10; j++) g_off[base + j] = pre + local[j];
    }
    if (t == 0) g_off[NN] = EE;
}

__global__ void k_fill_csr(const int* __restrict__ src, const int* __restrict__ dst) {
    int e = blockIdx.x * blockDim.x + threadIdx.x;
    if (e < EE) {
        int d = dst[e];
        int p = g_off[d] + atomicAdd(&g_cur[d], 1);
        g_csr[p] = src[e];
    }
}

// ------------- fused prep: x -> fp16 + W1 transpose+split (one launch) -------------
#define XSPLIT_BLOCKS ((NN * DIN) / 256)               // 5000
__global__ __launch_bounds__(256) void k_prep1(
    const float* __restrict__ x, const float* __restrict__ W1)
{
    int b = blockIdx.x;
    if (b < XSPLIT_BLOCKS) {
        int i = b * 256 + threadIdx.x;
        g_x16[i] = __float2half_rn(x[i]);
    } else {
        __shared__ float tile[32][33];
        int b2 = b - XSPLIT_BLOCKS;                    // 0..127
        int n0 = (b2 & 31) * 32;                       // HH/32 = 32 n-tiles
        int k0 = (b2 >> 5) * 32;                       // DIN/32 = 4 k-tiles
        int tx = threadIdx.x & 31, ty = threadIdx.x >> 5;   // 32 x 8
        #pragma unroll
        for (int i = 0; i < 32; i += 8)
            tile[ty + i][tx] = W1[(size_t)(k0 + ty + i) * HH + n0 + tx];
        __syncthreads();
        #pragma unroll
        for (int i = 0; i < 32; i += 8) {
            float w = tile[tx][ty + i];                // k = k0+tx, n = n0+ty+i
            __half h = __float2half_rn(w);
            g_w1thi[(size_t)(n0 + ty + i) * DIN + k0 + tx] = h;
            g_w1tlo[(size_t)(n0 + ty + i) * DIN + k0 + tx] =
                __float2half_rn(w - __half2float(h));
        }
    }
}

// transpose + split: W [K,N] fp32 row-major -> Thi/Tlo [N,K] fp16
__global__ void k_wsplit_t(const float* __restrict__ W,
                           __half* __restrict__ Thi,
                           __half* __restrict__ Tlo, int K, int N) {
    __shared__ float tile[32][33];
    int n0 = blockIdx.x * 32, k0 = blockIdx.y * 32;
    int tx = threadIdx.x, ty = threadIdx.y;       // 32 x 8
    #pragma unroll
    for (int i = 0; i < 32; i += 8)
        tile[ty + i][tx] = W[(size_t)(k0 + ty + i) * N + n0 + tx];
    __syncthreads();
    #pragma unroll
    for (int i = 0; i < 32; i += 8) {
        float w = tile[tx][ty + i];               // k = k0+tx, n = n0+ty+i
        __half h = __float2half_rn(w);
        Thi[(size_t)(n0 + ty + i) * K + k0 + tx] = h;
        Tlo[(size_t)(n0 + ty + i) * K + k0 + tx] =
            __float2half_rn(w - __half2float(h));
    }
}

// ---------------- tensor-core GEMM via mma.sync (fp16 2-term scheme) ----------------
// C[r,c] = fp16((A @ (Whi+Wlo)^T)[r,c] * scale[r]). A fp16 [M,K] row-major,
// Whi/Wlo fp16 [HH,K] row-major. A tile shared by both passes; single fp32 acc.
// __launch_bounds__(256,2) keeps regs <= 128 so 2 CTAs co-reside per SM.
#define GBM 128
#define GBN 128
#define TILE_BYTES 16384                           // 128 rows x 128B
#define STAGE_BYTES (3 * TILE_BYTES)               // A + Bhi + Blo = 48KB
#define SM_TOTAL    (2 * STAGE_BYTES)              // double buffered = 96KB

__device__ __forceinline__ void stage_load_async(
    const __half* __restrict__ A, const __half* __restrict__ Bhi,
    const __half* __restrict__ Blo,
    uint32_t base, int bm, int bn, int k0, int M, int K, int tid)
{
    #pragma unroll
    for (int i = 0; i < 4; i++) {
        int idx = i * 256 + tid;                  // 1024 16B chunks per tile
        int r = idx >> 3, c = idx & 7;
        uint32_t off = (uint32_t)(r * 128 + ((c ^ (r & 7)) * 16));  // XOR swizzle
        int rg = bm + r;
        int pa = (rg < M) ? 16 : 0;
        if (rg >= M) rg = M - 1;                  // clamp pointer, src_size=0 zero-fills
        const void* ga = A + (size_t)rg * K + k0 + c * 8;
        asm volatile("cp.async.cg.shared.global [%0], [%1], 16, %2;"
                     :: "r"(base + off), "l"(ga), "r"(pa) : "memory");
        const void* gh = Bhi + (size_t)(bn + r) * K + k0 + c * 8;
        asm volatile("cp.async.cg.shared.global [%0], [%1], 16;"
                     :: "r"(base + TILE_BYTES + off), "l"(gh) : "memory");
        const void* gl = Blo + (size_t)(bn + r) * K + k0 + c * 8;
        asm volatile("cp.async.cg.shared.global [%0], [%1], 16;"
                     :: "r"(base + 2 * TILE_BYTES + off), "l"(gl) : "memory");
    }
}

__global__ __launch_bounds__(256, 2) void k_tgemm(
    const __half* __restrict__ A, const __half* __restrict__ Bhi,
    const __half* __restrict__ Blo,
    __half* __restrict__ C, const float* __restrict__ scale, int M, int K)
{
    extern __shared__ char smem[];
    uint32_t sb = (uint32_t)__cvta_generic_to_shared(smem);
    int tid  = threadIdx.x;
    int lane = tid & 31;
    int wid  = tid >> 5;
    int wm   = (wid >> 2) * 64;                   // warp M offset (0 / 64)
    int wn   = (wid & 3) * 32;                    // warp N offset (0..96)
    int bn = blockIdx.x * GBN, bm = blockIdx.y * GBM;

    float acc[4][4][4];
    #pragma unroll
    for (int a = 0; a < 4; a++)
        #pragma unroll
        for (int b = 0; b < 4; b++)
            #pragma unroll
            for (int c = 0; c < 4; c++) acc[a][b][c] = 0.f;

    const int S = K >> 6;                         // 64-wide K chunks (single pass)

    // A ldmatrix addressing (x4: rows 0-15 x k-halves)
    int arow = wm + (lane & 15);
    int acol_half = lane >> 4;
    // B ldmatrix addressing (x4: two nt tiles x two k-halves per instruction)
    int brow4 = wn + ((lane >> 4) << 3) + (lane & 7);
    int bcol_half = (lane >> 3) & 1;

    {   // prologue: stage 0
        stage_load_async(A, Bhi, Blo, sb, bm, bn, 0, M, K, tid);
        asm volatile("cp.async.commit_group;" ::: "memory");
    }

    for (int s = 0; s < S; s++) {
        if (s + 1 < S) {
            uint32_t base = sb + (uint32_t)((s + 1) & 1) * STAGE_BYTES;
            stage_load_async(A, Bhi, Blo, base, bm, bn, (s + 1) << 6, M, K, tid);
            asm volatile("cp.async.commit_group;" ::: "memory");
            asm volatile("cp.async.wait_group 1;" ::: "memory");
        } else {
            asm volatile("cp.async.wait_group 0;" ::: "memory");
        }
        __syncthreads();

        uint32_t aB  = sb + (uint32_t)(s & 1) * STAGE_BYTES;
        uint32_t bhB = aB + TILE_BYTES;
        uint32_t blB = aB + 2 * TILE_BYTES;

        #pragma unroll
        for (int ks = 0; ks < 4; ks++) {
            uint32_t af[4][4];
            #pragma unroll
            for (int mt = 0; mt < 4; mt++) {
                int row = arow + mt * 16;
                int c = 2 * ks + acol_half;
                uint32_t off = (uint32_t)(row * 128 + ((c ^ (row & 7)) * 16));
                asm volatile("ldmatrix.sync.aligned.m8n8.x4.shared.b16 {%0,%1,%2,%3}, [%4];"
                             : "=r"(af[mt][0]), "=r"(af[mt][1]),
                               "=r"(af[mt][2]), "=r"(af[mt][3])
                             : "r"(aB + off));
            }
            // pass 1: B-hi (bf live range ends before pass 2 loads B-lo)
            {
                uint32_t bf[4][2];
                #pragma unroll
                for (int nt2 = 0; nt2 < 2; nt2++) {
                    int row = brow4 + nt2 * 16;
                    int c = 2 * ks + bcol_half;
                    uint32_t off = (uint32_t)(row * 128 + ((c ^ (row & 7)) * 16));
                    asm volatile("ldmatrix.sync.aligned.m8n8.x4.shared.b16 {%0,%1,%2,%3}, [%4];"
                                 : "=r"(bf[nt2 * 2][0]), "=r"(bf[nt2 * 2][1]),
                                   "=r"(bf[nt2 * 2 + 1][0]), "=r"(bf[nt2 * 2 + 1][1])
                                 : "r"(bhB + off));
                }
                #pragma unroll
                for (int mt = 0; mt < 4; mt++)
                    #pragma unroll
                    for (int nt = 0; nt < 4; nt++)
                        asm volatile(
                            "mma.sync.aligned.m16n8k16.row.col.f32.f16.f16.f32 "
                            "{%0,%1,%2,%3}, {%4,%5,%6,%7}, {%8,%9}, {%0,%1,%2,%3};"
                            : "+f"(acc[mt][nt][0]), "+f"(acc[mt][nt][1]),
                              "+f"(acc[mt][nt][2]), "+f"(acc[mt][nt][3])
                            : "r"(af[mt][0]), "r"(af[mt][1]), "r"(af[mt][2]), "r"(af[mt][3]),
                              "r"(bf[nt][0]), "r"(bf[nt][1]));
            }
            // pass 2: B-lo
            {
                uint32_t bf[4][2];
                #pragma unroll
                for (int nt2 = 0; nt2 < 2; nt2++) {
                    int row = brow4 + nt2 * 16;
                    int c = 2 * ks + bcol_half;
                    uint32_t off = (uint32_t)(row * 128 + ((c ^ (row & 7)) * 16));
                    asm volatile("ldmatrix.sync.aligned.m8n8.x4.shared.b16 {%0,%1,%2,%3}, [%4];"
                                 : "=r"(bf[nt2 * 2][0]), "=r"(bf[nt2 * 2][1]),
                                   "=r"(bf[nt2 * 2 + 1][0]), "=r"(bf[nt2 * 2 + 1][1])
                                 : "r"(blB + off));
                }
                #pragma unroll
                for (int mt = 0; mt < 4; mt++)
                    #pragma unroll
                    for (int nt = 0; nt < 4; nt++)
                        asm volatile(
                            "mma.sync.aligned.m16n8k16.row.col.f32.f16.f16.f32 "
                            "{%0,%1,%2,%3}, {%4,%5,%6,%7}, {%8,%9}, {%0,%1,%2,%3};"
                            : "+f"(acc[mt][nt][0]), "+f"(acc[mt][nt][1]),
                              "+f"(acc[mt][nt][2]), "+f"(acc[mt][nt][3])
                            : "r"(af[mt][0]), "r"(af[mt][1]), "r"(af[mt][2]), "r"(af[mt][3]),
                              "r"(bf[nt][0]), "r"(bf[nt][1]));
            }
        }
        __syncthreads();
    }

    // epilogue: scale rows by dinv (this IS the dinv[src] factor), store fp16
    int g  = lane >> 2;
    int tq = lane & 3;
    #pragma unroll
    for (int mt = 0; mt < 4; mt++) {
        int r0 = bm + wm + mt * 16 + g;
        int r1 = r0 + 8;
        float s0 = (r0 < M) ? scale[r0] : 0.f;
        float s1 = (r1 < M) ? scale[r1] : 0.f;
        #pragma unroll
        for (int nt = 0; nt < 4; nt++) {
            int col = bn + wn + nt * 8 + tq * 2;
            if (r0 < M) {
                __half2 v = __floats2half2_rn(acc[mt][nt][0] * s0, acc[mt][nt][1] * s0);
                *(__half2*)(C + (size_t)r0 * HH + col) = v;
            }
            if (r1 < M) {
                __half2 v = __floats2half2_rn(acc[mt][nt][2] * s1, acc[mt][nt][3] * s1);
                *(__half2*)(C + (size_t)r1 * HH + col) = v;
            }
        }
    }
}

// ---------------- block reduce ----------------
__device__ __forceinline__ float block_sum256(float v, float* sm) {
    #pragma unroll
    for (int o = 16; o > 0; o >>= 1) v += __shfl_down_sync(0xffffffffu, v, o);
    int w = threadIdx.x >> 5;
    if ((threadIdx.x & 31) == 0) sm[w] = v;
    __syncthreads();
    float r;
    if (threadIdx.x < 8) {
        float x = sm[threadIdx.x];
        #pragma unroll
        for (int o = 4; o > 0; o >>= 1) x += __shfl_down_sync(0xffu, x, o);
        if (threadIdx.x == 0) sm[0] = x;
    }
    __syncthreads();
    r = sm[0];
    __syncthreads();
    return r;
}

__device__ __forceinline__ void acc_u2(float4& acc, uint2 raw) {
    float2 f0 = __half22float2(*(__half2*)&raw.x);
    float2 f1 = __half22float2(*(__half2*)&raw.y);
    acc.x += f0.x; acc.y += f0.y; acc.z += f1.x; acc.w += f1.y;
}

// ---- fused: gather-sum(CSR, fp16 rows pre-scaled by dinv) + bias + res + LN + ReLU ----
// hw rows are 1024 fp16 = 256 uint2; thread t owns uint2 #t (4 values).
__global__ __launch_bounds__(256) void k_agg_ln(
    const uint2* __restrict__ hw,
    const float* __restrict__ bias,
    const float* __restrict__ res,            // nullable
    const float* __restrict__ gamma,
    const float* __restrict__ beta,
    float* __restrict__ out,
    float* __restrict__ save_pre,             // nullable
    __half2* __restrict__ o16)                // nullable: fp16 copy of out (GEMM A)
{
    __shared__ int   se[256];
    __shared__ float sm[8];
    int i = blockIdx.x;
    int t = threadIdx.x;

    int e0 = g_off[i], e1 = g_off[i + 1];
    float4 acc = make_float4(0.f, 0.f, 0.f, 0.f);
    acc_u2(acc, hw[(size_t)i * 256 + t]);         // self loop (pre-scaled)
    for (int base = e0; base < e1; base += 256) {
        int ne = min(256, e1 - base);
        if (t < ne) se[t] = g_csr[base + t];
        __syncthreads();
        int e = 0;
        // manual 8x unroll: keep 8 independent LDG.64 in flight
        for (; e + 8 <= ne; e += 8) {
            uint2 v0 = hw[(size_t)se[e]     * 256 + t];
            uint2 v1 = hw[(size_t)se[e + 1] * 256 + t];
            uint2 v2 = hw[(size_t)se[e + 2] * 256 + t];
            uint2 v3 = hw[(size_t)se[e + 3] * 256 + t];
            uint2 v4 = hw[(size_t)se[e + 4] * 256 + t];
            uint2 v5 = hw[(size_t)se[e + 5] * 256 + t];
            uint2 v6 = hw[(size_t)se[e + 6] * 256 + t];
            uint2 v7 = hw[(size_t)se[e + 7] * 256 + t];
            acc_u2(acc, v0); acc_u2(acc, v1); acc_u2(acc, v2); acc_u2(acc, v3);
            acc_u2(acc, v4); acc_u2(acc, v5); acc_u2(acc, v6); acc_u2(acc, v7);
        }
        for (; e < ne; e++) acc_u2(acc, hw[(size_t)se[e] * 256 + t]);
        __syncthreads();
    }

    float di = g_dinv[i];
    float4 bi = ((const float4*)bias)[t];
    float4 y;
    y.x = acc.x * di + bi.x;
    y.y = acc.y * di + bi.y;
    y.z = acc.z * di + bi.z;
    y.w = acc.w * di + bi.w;
    if (res) {
        float4 r = ((const float4*)res)[(size_t)i * HV + t];
        y.x += r.x; y.y += r.y; y.z += r.z; y.w += r.w;
    }
    if (save_pre) ((float4*)save_pre)[(size_t)i * HV + t] = y;

    float s = y.x + y.y + y.z + y.w;
    float mean = block_sum256(s, sm) * (1.0f / HH);
    float dx = y.x - mean, dy = y.y - mean, dz = y.z - mean, dw = y.w - mean;
    float sq = dx*dx + dy*dy + dz*dz + dw*dw;
    float var = block_sum256(sq, sm) * (1.0f / HH);
    float inv = rsqrtf(var + EPSL);

    float4 g = ((const float4*)gamma)[t];
    float4 b = ((const float4*)beta)[t];
    float4 o;
    o.x = fmaxf(dx * inv * g.x + b.x, 0.f);
    o.y = fmaxf(dy * inv * g.y + b.y, 0.f);
    o.z = fmaxf(dz * inv * g.z + b.z, 0.f);
    o.w = fmaxf(dw * inv * g.w + b.w, 0.f);
    ((float4*)out)[(size_t)i * HV + t] = o;

    if (o16) {
        size_t bx = (size_t)i * (HH / 2) + t * 2;
        o16[bx]     = __floats2half2_rn(o.x, o.y);
        o16[bx + 1] = __floats2half2_rn(o.z, o.w);
    }
}

// ---------------- pooling ----------------
__global__ void k_find_starts(const int* __restrict__ batch) {
    int g = threadIdx.x;
    if (g == GG) { g_start[GG] = NN; return; }
    if (g < GG) {
        int lo = 0, hi = NN;
        while (lo < hi) {
            int mid = (lo + hi) >> 1;
            if (batch[mid] < g) lo = mid + 1; else hi = mid;
        }
        g_start[g] = lo;
    }
}

#define SPLITS 8
__global__ __launch_bounds__(256) void k_pool_partial(const float* __restrict__ emb) {
    int g  = blockIdx.x / SPLITS;
    int sp = blockIdx.x % SPLITS;
    int s0 = g_start[g], s1 = g_start[g + 1];
    int cnt = s1 - s0;
    int per = (cnt + SPLITS - 1) / SPLITS;
    int a = s0 + sp * per;
    int b = min(s1, a + per);
    int t = threadIdx.x;
    float4 acc = make_float4(0.f, 0.f, 0.f, 0.f);
    for (int i = a; i < b; i++) {
        float4 v = ((const float4*)emb)[(size_t)i * HV + t];
        acc.x += v.x; acc.y += v.y; acc.z += v.z; acc.w += v.w;
    }
    float* dstp = &g_pool[g * HH + t * 4];
    atomicAdd(dstp + 0, acc.x);
    atomicAdd(dstp + 1, acc.y);
    atomicAdd(dstp + 2, acc.z);
    atomicAdd(dstp + 3, acc.w);
}

__global__ void k_fin_pool(float* __restrict__ graph_out, float* __restrict__ v0) {
    int g = blockIdx.x;
    int t = threadIdx.x;
    float c = fmaxf((float)(g_start[g + 1] - g_start[g]), 1.0f);
    float invc = 1.0f / c;
    float4 v = ((const float4*)g_pool)[g * HV + t];
    v.x *= invc; v.y *= invc; v.z *= invc; v.w *= invc;
    ((float4*)graph_out)[g * HV + t] = v;
    ((float4*)v0)[g * HV + t] = v;
}

// ---------------- tiny MLP (k-split for parallelism) ----------------
__global__ __launch_bounds__(128) void k_mlp_partial(
    const float* __restrict__ vin, const float* __restrict__ W)
{
    __shared__ __align__(16) float vsT[128 * GG];   // [k][g], 4 KB
    int t  = threadIdx.x;
    int jb = blockIdx.x, ks = blockIdx.y;
    int kbase = ks * 128;
    for (int i = t; i < 128 * GG; i += 128) {
        int k = i >> 3, g = i & 7;
        vsT[i] = vin[g * HH + kbase + k];
    }
    __syncthreads();
    int j = jb * 128 + t;
    float acc[GG] = {};
    #pragma unroll 16
    for (int k = 0; k < 128; k++) {
        float w = W[(size_t)(kbase + k) * HH + j];
        float4 a0 = *(const float4*)&vsT[k * 8];
        float4 a1 = *(const float4*)&vsT[k * 8 + 4];
        acc[0] += a0.x * w; acc[1] += a0.y * w; acc[2] += a0.z * w; acc[3] += a0.w * w;
        acc[4] += a1.x * w; acc[5] += a1.y * w; acc[6] += a1.z * w; acc[7] += a1.w * w;
    }
    #pragma unroll
    for (int g = 0; g < GG; g++)
        g_mpart[ks][g * HH + j] = acc[g];
}

__global__ __launch_bounds__(256) void k_mlp_fin(
    const float* __restrict__ b, float* __restrict__ vout)
{
    int i = blockIdx.x * blockDim.x + threadIdx.x;   // over GG*HH
    int j = i & (HH - 1);
    float s = 0.f;
    #pragma unroll
    for (int ks = 0; ks < 8; ks++) s += g_mpart[ks][i];
    vout[i] = fmaxf(s + b[j], 0.f);
}

__global__ __launch_bounds__(256) void k_head(
    const float* __restrict__ v, const float* __restrict__ wo,
    const float* __restrict__ bo, float* __restrict__ sv)
{
    __shared__ float sm[8];
    int t = threadIdx.x;
    float4 w4 = ((const float4*)wo)[t];
    for (int g = 0; g < GG; g++) {
        float4 x = ((const float4*)v)[g * HV + t];
        float s = x.x * w4.x + x.y * w4.y + x.z * w4.z + x.w * w4.w;
        float tot = block_sum256(s, sm);
        if (t == 0) sv[g] = tot + bo[0];
    }
}

// ---------------- launch ----------------
extern "C" void kernel_launch(void* const* d_in, const int* in_sizes, int n_in,
                              void* d_out, int out_size) {
    const float* x     = (const float*)d_in[0];
    const int*   ei    = (const int*)  d_in[1];
    const int*   batch = (const int*)  d_in[2];
    const float* W1    = (const float*)d_in[3];
    const float* b1    = (const float*)d_in[4];
    const float* Wh    = (const float*)d_in[5];
    const float* bh    = (const float*)d_in[6];
    const float* lng   = (const float*)d_in[7];
    const float* lnb   = (const float*)d_in[8];
    const float* vW    = (const float*)d_in[9];
    const float* vb    = (const float*)d_in[10];
    const float* vWo   = (const float*)d_in[11];
    const float* vbo   = (const float*)d_in[12];

    const int* src = ei;
    const int* dst = ei + EE;

    float* node_out  = (float*)d_out;
    float* graph_out = node_out + (size_t)NN * HH;
    float* sv_out    = graph_out + GG * HH;

    // resolve true DEVICE addresses of __device__ symbols (ATS pitfall!)
    float *x1, *h, *dinv, *vbuf, *poolp;
    __half *hw, *a16, *x16, *wthi, *wtlo, *w1thi, *w1tlo;
    int   *cntp;
    cudaGetSymbolAddress((void**)&hw,    g_hw);
    cudaGetSymbolAddress((void**)&x1,    g_x1);
    cudaGetSymbolAddress((void**)&h,     g_h);
    cudaGetSymbolAddress((void**)&dinv,  g_dinv);
    cudaGetSymbolAddress((void**)&vbuf,  g_vbuf);
    cudaGetSymbolAddress((void**)&poolp, g_pool);
    cudaGetSymbolAddress((void**)&cntp,  g_cnt);
    cudaGetSymbolAddress((void**)&a16,   g_a16);
    cudaGetSymbolAddress((void**)&x16,   g_x16);
    cudaGetSymbolAddress((void**)&wthi,  g_wthi);
    cudaGetSymbolAddress((void**)&wtlo,  g_wtlo);
    cudaGetSymbolAddress((void**)&w1thi, g_w1thi);
    cudaGetSymbolAddress((void**)&w1tlo, g_w1tlo);
    float* vbuf0 = vbuf;
    float* vbuf1 = vbuf + GG * HH;

    cudaFuncSetAttribute(k_tgemm, cudaFuncAttributeMaxDynamicSharedMemorySize, SM_TOTAL);

    dim3 tg(HH / GBN, (NN + GBM - 1) / GBM);   // (8, 79)

    // memset nodes (not kernel launches) — zero degree counters and pool buffer
    cudaMemsetAsync(cntp,  0, NN * sizeof(int));
    cudaMemsetAsync(poolp, 0, GG * HH * sizeof(float));

    // ---- kernel launches 1-3, then layer-1 GEMM as launch #4 (ncu window) ----
    k_prep1<<<XSPLIT_BLOCKS + 128, 256>>>(x, W1);                            // 1
    k_count_deg<<<(EE + 255) / 256, 256>>>(dst);                             // 2
    k_fin_dinv<<<(NN + 255) / 256, 256>>>();                                 // 3
    k_tgemm<<<tg, 256, SM_TOTAL>>>(x16, w1thi, w1tlo, hw, dinv, NN, DIN);    // 4

    // ---- rest of CSR + weight prep (overlap region) ----
    k_scan_off<<<1, 1024>>>();
    k_fill_csr<<<(EE + 255) / 256, 256>>>(src, dst);
    for (int l = 0; l < 3; l++)
        k_wsplit_t<<<dim3(HH / 32, HH / 32), dim3(32, 8)>>>(
            Wh + (size_t)l * HH * HH, wthi + (size_t)l * HH * HH,
            wtlo + (size_t)l * HH * HH, HH, HH);

    // ---- layer 1 agg ----
    k_agg_ln<<<NN, 256>>>((const uint2*)hw, b1, nullptr,
                          lng + 0 * HH, lnb + 0 * HH, h, x1, (__half2*)a16);

    // ---- layer 2 ----
    k_tgemm<<<tg, 256, SM_TOTAL>>>(a16, wthi + 0 * (size_t)HH * HH,
                                   wtlo + 0 * (size_t)HH * HH, hw, dinv, NN, HH);
    k_agg_ln<<<NN, 256>>>((const uint2*)hw, bh + 0 * HH, x1,
                          lng + 1 * HH, lnb + 1 * HH, h, nullptr, (__half2*)a16);

    // ---- layer 3 ----
    k_tgemm<<<tg, 256, SM_TOTAL>>>(a16, wthi + 1 * (size_t)HH * HH,
                                   wtlo + 1 * (size_t)HH * HH, hw, dinv, NN, HH);
    k_agg_ln<<<NN, 256>>>((const uint2*)hw, bh + 1 * HH, x1,
                          lng + 2 * HH, lnb + 2 * HH, h, nullptr, (__half2*)a16);

    // ---- layer 4 ----
    k_tgemm<<<tg, 256, SM_TOTAL>>>(a16, wthi + 2 * (size_t)HH * HH,
                                   wtlo + 2 * (size_t)HH * HH, hw, dinv, NN, HH);
    k_agg_ln<<<NN, 256>>>((const uint2*)hw, bh + 2 * HH, h,
                          lng + 3 * HH, lnb + 3 * HH, node_out, nullptr, nullptr);

    // ---- pooling ----
    k_find_starts<<<1, 32>>>(batch);
    k_pool_partial<<<GG * SPLITS, 256>>>(node_out);
    k_fin_pool<<<GG, 256>>>(graph_out, vbuf0);

    // ---- value MLP (6 layers, k-split) + head ----
    for (int i = 0; i < 6; i++) {
        const float* vin = (i & 1) ? vbuf1 : vbuf0;
        float* vout      = (i & 1) ? vbuf0 : vbuf1;
        k_mlp_partial<<<dim3(HH / 128, 8), 128>>>(vin, vW + (size_t)i * HH * HH);
        k_mlp_fin<<<(GG * HH) / 256, 256>>>(vb + i * HH, vout);
    }
    k_head<<<1, 256>>>(vbuf0, vWo, vbo, sv_out);
}

// round 16
// speedup vs baseline: 1.8647x; 1.8647x over previous
#include <cuda_runtime.h>
#include <cuda_bf16.h>
#include <cuda_fp16.h>
#include <cstdint>

#define NN   10000
#define EE   160000
#define DIN  128
#define HH   1024
#define GG   8
#define HV   (HH/4)   // 256 float4 per row
#define EPSL 1e-5f

// ---------------- device scratch (static; no allocation allowed) ----------------
__device__ float g_dinv[NN];
__device__ int   g_cnt[NN];
__device__ int   g_off[NN + 1];
__device__ int   g_cur[NN];
__device__ int   g_csr[EE];
__device__ __half g_hw[(size_t)NN * HH]; // (A@W) * dinv[row], fp16 (agg-only operand)
__device__ float g_x1[(size_t)NN * HH];   // saved x1 for residuals (fp32)
__device__ float g_h [(size_t)NN * HH];   // current activation (fp32)
__device__ float g_pool[GG * HH];
__device__ int   g_start[GG + 1];
__device__ float g_vbuf[2][GG * HH];
__device__ float g_mpart[8][GG * HH];     // MLP k-split partials
// fp16 operand buffers for tensor-core GEMMs (plain fp16, single pass)
__device__ __half g_a16[(size_t)NN * HH];      // activations, fp16
__device__ __half g_x16[(size_t)NN * DIN];     // input x, fp16
__device__ __half g_wt[3 * (size_t)HH * HH];   // Wh transposed [N,K], fp16
__device__ __half g_w1t[(size_t)HH * DIN];     // W1 transposed [1024,128], fp16

// ---------------- degree / CSR construction ----------------
__global__ void k_count_deg(const int* __restrict__ dst) {
    int e = blockIdx.x * blockDim.x + threadIdx.x;
    if (e < EE) atomicAdd(&g_cnt[dst[e]], 1);
}

__global__ void k_fin_dinv() {
    int i = blockIdx.x * blockDim.x + threadIdx.x;
    if (i < NN) {
        float deg = (float)(g_cnt[i] + 1);
        g_dinv[i] = rsqrtf(deg);
        g_cur[i]  = 0;
    }
}

__global__ void k_scan_off() {
    __shared__ int partial[1024];
    int t = threadIdx.x;
    int base = t * 10;
    int local[10];
    int s = 0;
    if (t < 1000) {
        #pragma unroll
        for (int j = 0; j < 10; j++) { local[j] = s; s += g_cnt[base + j]; }
    }
    partial[t] = (t < 1000) ? s : 0;
    __syncthreads();
    for (int d = 1; d < 1024; d <<= 1) {
        int v = partial[t];
        int add = (t >= d) ? partial[t - d] : 0;
        __syncthreads();
        partial[t] = v + add;
        __syncthreads();
    }
    int pre = (t > 0) ? partial[t - 1] : 0;
    if (t < 1000) {
        #pragma unroll
        for (int j = 0; j < 10; j++) g_off[base + j] = pre + local[j];
    }
    if (t == 0) g_off[NN] = EE;
}

__global__ void k_fill_csr(const int* __restrict__ src, const int* __restrict__ dst) {
    int e = blockIdx.x * blockDim.x + threadIdx.x;
    if (e < EE) {
        int d = dst[e];
        int p = g_off[d] + atomicAdd(&g_cur[d], 1);
        g_csr[p] = src[e];
    }
}

// ------------- fused prep: x -> fp16 + W1 transpose (one launch) -------------
#define XSPLIT_BLOCKS ((NN * DIN) / 256)               // 5000
__global__ __launch_bounds__(256) void k_prep1(
    const float* __restrict__ x, const float* __restrict__ W1)
{
    int b = blockIdx.x;
    if (b < XSPLIT_BLOCKS) {
        int i = b * 256 + threadIdx.x;
        g_x16[i] = __float2half_rn(x[i]);
    } else {
        __shared__ float tile[32][33];
        int b2 = b - XSPLIT_BLOCKS;                    // 0..127
        int n0 = (b2 & 31) * 32;                       // HH/32 = 32 n-tiles
        int k0 = (b2 >> 5) * 32;                       // DIN/32 = 4 k-tiles
        int tx = threadIdx.x & 31, ty = threadIdx.x >> 5;   // 32 x 8
        #pragma unroll
        for (int i = 0; i < 32; i += 8)
            tile[ty + i][tx] = W1[(size_t)(k0 + ty + i) * HH + n0 + tx];
        __syncthreads();
        #pragma unroll
        for (int i = 0; i < 32; i += 8)
            g_w1t[(size_t)(n0 + ty + i) * DIN + k0 + tx] =
                __float2half_rn(tile[tx][ty + i]);
    }
}

// transpose: W [K,N] fp32 row-major -> T [N,K] fp16
__global__ void k_wt16(const float* __restrict__ W,
                       __half* __restrict__ T, int K, int N) {
    __shared__ float tile[32][33];
    int n0 = blockIdx.x * 32, k0 = blockIdx.y * 32;
    int tx = threadIdx.x, ty = threadIdx.y;       // 32 x 8
    #pragma unroll
    for (int i = 0; i < 32; i += 8)
        tile[ty + i][tx] = W[(size_t)(k0 + ty + i) * N + n0 + tx];
    __syncthreads();
    #pragma unroll
    for (int i = 0; i < 32; i += 8)
        T[(size_t)(n0 + ty + i) * K + k0 + tx] =
            __float2half_rn(tile[tx][ty + i]);
}

// ---------------- tensor-core GEMM via mma.sync (plain fp16, single pass) --------
// C[r,c] = fp16((A @ Wt^T)[r,c] * scale[r]). A fp16 [M,K] row-major,
// Wt fp16 [HH,K] row-major. fp32 accumulators.
#define GBM 128
#define GBN 128
#define TILE_BYTES 16384                           // 128 rows x 128B
#define STAGE_BYTES (2 * TILE_BYTES)               // A + B = 32KB
#define SM_TOTAL    (2 * STAGE_BYTES)              // double buffered = 64KB

__device__ __forceinline__ void stage_load_async(
    const __half* __restrict__ A, const __half* __restrict__ B,
    uint32_t base, int bm, int bn, int k0, int M, int K, int tid)
{
    #pragma unroll
    for (int i = 0; i < 4; i++) {
        int idx = i * 256 + tid;                  // 1024 16B chunks per tile
        int r = idx >> 3, c = idx & 7;
        uint32_t off = (uint32_t)(r * 128 + ((c ^ (r & 7)) * 16));  // XOR swizzle
        int rg = bm + r;
        int pa = (rg < M) ? 16 : 0;
        if (rg >= M) rg = M - 1;                  // clamp pointer, src_size=0 zero-fills
        const void* ga = A + (size_t)rg * K + k0 + c * 8;
        asm volatile("cp.async.cg.shared.global [%0], [%1], 16, %2;"
                     :: "r"(base + off), "l"(ga), "r"(pa) : "memory");
        const void* gb = B + (size_t)(bn + r) * K + k0 + c * 8;
        asm volatile("cp.async.cg.shared.global [%0], [%1], 16;"
                     :: "r"(base + TILE_BYTES + off), "l"(gb) : "memory");
    }
}

__global__ __launch_bounds__(256) void k_tgemm(
    const __half* __restrict__ A, const __half* __restrict__ B,
    __half* __restrict__ C, const float* __restrict__ scale, int M, int K)
{
    extern __shared__ char smem[];
    uint32_t sb = (uint32_t)__cvta_generic_to_shared(smem);
    int tid  = threadIdx.x;
    int lane = tid & 31;
    int wid  = tid >> 5;
    int wm   = (wid >> 2) * 64;                   // warp M offset (0 / 64)
    int wn   = (wid & 3) * 32;                    // warp N offset (0..96)
    int bn = blockIdx.x * GBN, bm = blockIdx.y * GBM;

    float acc[4][4][4];
    #pragma unroll
    for (int a = 0; a < 4; a++)
        #pragma unroll
        for (int b = 0; b < 4; b++)
            #pragma unroll
            for (int c = 0; c < 4; c++) acc[a][b][c] = 0.f;

    const int S = K >> 6;                         // 64-wide K chunks

    // A ldmatrix addressing (x4: rows 0-15 x k-halves)
    int arow = wm + (lane & 15);
    int acol_half = lane >> 4;
    // B ldmatrix addressing (x4: two nt tiles x two k-halves per instruction)
    int brow4 = wn + ((lane >> 4) << 3) + (lane & 7);
    int bcol_half = (lane >> 3) & 1;

    {   // prologue: stage 0
        stage_load_async(A, B, sb, bm, bn, 0, M, K, tid);
        asm volatile("cp.async.commit_group;" ::: "memory");
    }

    for (int s = 0; s < S; s++) {
        if (s + 1 < S) {
            uint32_t base = sb + (uint32_t)((s + 1) & 1) * STAGE_BYTES;
            stage_load_async(A, B, base, bm, bn, (s + 1) << 6, M, K, tid);
            asm volatile("cp.async.commit_group;" ::: "memory");
            asm volatile("cp.async.wait_group 1;" ::: "memory");
        } else {
            asm volatile("cp.async.wait_group 0;" ::: "memory");
        }
        __syncthreads();

        uint32_t aB = sb + (uint32_t)(s & 1) * STAGE_BYTES;
        uint32_t bB = aB + TILE_BYTES;

        #pragma unroll
        for (int ks = 0; ks < 4; ks++) {
            uint32_t af[4][4];
            #pragma unroll
            for (int mt = 0; mt < 4; mt++) {
                int row = arow + mt * 16;
                int c = 2 * ks + acol_half;
                uint32_t off = (uint32_t)(row * 128 + ((c ^ (row & 7)) * 16));
                asm volatile("ldmatrix.sync.aligned.m8n8.x4.shared.b16 {%0,%1,%2,%3}, [%4];"
                             : "=r"(af[mt][0]), "=r"(af[mt][1]),
                               "=r"(af[mt][2]), "=r"(af[mt][3])
                             : "r"(aB + off));
            }
            uint32_t bf[4][2];
            #pragma unroll
            for (int nt2 = 0; nt2 < 2; nt2++) {
                int row = brow4 + nt2 * 16;
                int c = 2 * ks + bcol_half;
                uint32_t off = (uint32_t)(row * 128 + ((c ^ (row & 7)) * 16));
                asm volatile("ldmatrix.sync.aligned.m8n8.x4.shared.b16 {%0,%1,%2,%3}, [%4];"
                             : "=r"(bf[nt2 * 2][0]), "=r"(bf[nt2 * 2][1]),
                               "=r"(bf[nt2 * 2 + 1][0]), "=r"(bf[nt2 * 2 + 1][1])
                             : "r"(bB + off));
            }
            #pragma unroll
            for (int mt = 0; mt < 4; mt++)
                #pragma unroll
                for (int nt = 0; nt < 4; nt++)
                    asm volatile(
                        "mma.sync.aligned.m16n8k16.row.col.f32.f16.f16.f32 "
                        "{%0,%1,%2,%3}, {%4,%5,%6,%7}, {%8,%9}, {%0,%1,%2,%3};"
                        : "+f"(acc[mt][nt][0]), "+f"(acc[mt][nt][1]),
                          "+f"(acc[mt][nt][2]), "+f"(acc[mt][nt][3])
                        : "r"(af[mt][0]), "r"(af[mt][1]), "r"(af[mt][2]), "r"(af[mt][3]),
                          "r"(bf[nt][0]), "r"(bf[nt][1]));
        }
        __syncthreads();
    }

    // epilogue: scale rows by dinv (this IS the dinv[src] factor), store fp16
    int g  = lane >> 2;
    int tq = lane & 3;
    #pragma unroll
    for (int mt = 0; mt < 4; mt++) {
        int r0 = bm + wm + mt * 16 + g;
        int r1 = r0 + 8;
        float s0 = (r0 < M) ? scale[r0] : 0.f;
        float s1 = (r1 < M) ? scale[r1] : 0.f;
        #pragma unroll
        for (int nt = 0; nt < 4; nt++) {
            int col = bn + wn + nt * 8 + tq * 2;
            if (r0 < M) {
                __half2 v = __floats2half2_rn(acc[mt][nt][0] * s0, acc[mt][nt][1] * s0);
                *(__half2*)(C + (size_t)r0 * HH + col) = v;
            }
            if (r1 < M) {
                __half2 v = __floats2half2_rn(acc[mt][nt][2] * s1, acc[mt][nt][3] * s1);
                *(__half2*)(C + (size_t)r1 * HH + col) = v;
            }
        }
    }
}

// ---------------- block reduce ----------------
__device__ __forceinline__ float block_sum256(float v, float* sm) {
    #pragma unroll
    for (int o = 16; o > 0; o >>= 1) v += __shfl_down_sync(0xffffffffu, v, o);
    int w = threadIdx.x >> 5;
    if ((threadIdx.x & 31) == 0) sm[w] = v;
    __syncthreads();
    float r;
    if (threadIdx.x < 8) {
        float x = sm[threadIdx.x];
        #pragma unroll
        for (int o = 4; o > 0; o >>= 1) x += __shfl_down_sync(0xffu, x, o);
        if (threadIdx.x == 0) sm[0] = x;
    }
    __syncthreads();
    r = sm[0];
    __syncthreads();
    return r;
}

__device__ __forceinline__ void acc_u2(float4& acc, uint2 raw) {
    float2 f0 = __half22float2(*(__half2*)&raw.x);
    float2 f1 = __half22float2(*(__half2*)&raw.y);
    acc.x += f0.x; acc.y += f0.y; acc.z += f1.x; acc.w += f1.y;
}

// ---- fused: gather-sum(CSR, fp16 rows pre-scaled by dinv) + bias + res + LN + ReLU ----
// hw rows are 1024 fp16 = 256 uint2; thread t owns uint2 #t (4 values).
__global__ __launch_bounds__(256) void k_agg_ln(
    const uint2* __restrict__ hw,
    const float* __restrict__ bias,
    const float* __restrict__ res,            // nullable
    const float* __restrict__ gamma,
    const float* __restrict__ beta,
    float* __restrict__ out,
    float* __restrict__ save_pre,             // nullable
    __half2* __restrict__ o16)                // nullable: fp16 copy of out (GEMM A)
{
    __shared__ int   se[256];
    __shared__ float sm[8];
    int i = blockIdx.x;
    int t = threadIdx.x;

    int e0 = g_off[i], e1 = g_off[i + 1];
    float4 acc = make_float4(0.f, 0.f, 0.f, 0.f);
    acc_u2(acc, hw[(size_t)i * 256 + t]);         // self loop (pre-scaled)
    for (int base = e0; base < e1; base += 256) {
        int ne = min(256, e1 - base);
        if (t < ne) se[t] = g_csr[base + t];
        __syncthreads();
        int e = 0;
        // manual 8x unroll: keep 8 independent LDG.64 in flight
        for (; e + 8 <= ne; e += 8) {
            uint2 v0 = hw[(size_t)se[e]     * 256 + t];
            uint2 v1 = hw[(size_t)se[e + 1] * 256 + t];
            uint2 v2 = hw[(size_t)se[e + 2] * 256 + t];
            uint2 v3 = hw[(size_t)se[e + 3] * 256 + t];
            uint2 v4 = hw[(size_t)se[e + 4] * 256 + t];
            uint2 v5 = hw[(size_t)se[e + 5] * 256 + t];
            uint2 v6 = hw[(size_t)se[e + 6] * 256 + t];
            uint2 v7 = hw[(size_t)se[e + 7] * 256 + t];
            acc_u2(acc, v0); acc_u2(acc, v1); acc_u2(acc, v2); acc_u2(acc, v3);
            acc_u2(acc, v4); acc_u2(acc, v5); acc_u2(acc, v6); acc_u2(acc, v7);
        }
        for (; e < ne; e++) acc_u2(acc, hw[(size_t)se[e] * 256 + t]);
        __syncthreads();
    }

    float di = g_dinv[i];
    float4 bi = ((const float4*)bias)[t];
    float4 y;
    y.x = acc.x * di + bi.x;
    y.y = acc.y * di + bi.y;
    y.z = acc.z * di + bi.z;
    y.w = acc.w * di + bi.w;
    if (res) {
        float4 r = ((const float4*)res)[(size_t)i * HV + t];
        y.x += r.x; y.y += r.y; y.z += r.z; y.w += r.w;
    }
    if (save_pre) ((float4*)save_pre)[(size_t)i * HV + t] = y;

    float s = y.x + y.y + y.z + y.w;
    float mean = block_sum256(s, sm) * (1.0f / HH);
    float dx = y.x - mean, dy = y.y - mean, dz = y.z - mean, dw = y.w - mean;
    float sq = dx*dx + dy*dy + dz*dz + dw*dw;
    float var = block_sum256(sq, sm) * (1.0f / HH);
    float inv = rsqrtf(var + EPSL);

    float4 g = ((const float4*)gamma)[t];
    float4 b = ((const float4*)beta)[t];
    float4 o;
    o.x = fmaxf(dx * inv * g.x + b.x, 0.f);
    o.y = fmaxf(dy * inv * g.y + b.y, 0.f);
    o.z = fmaxf(dz * inv * g.z + b.z, 0.f);
    o.w = fmaxf(dw * inv * g.w + b.w, 0.f);
    ((float4*)out)[(size_t)i * HV + t] = o;

    if (o16) {
        size_t bx = (size_t)i * (HH / 2) + t * 2;
        o16[bx]     = __floats2half2_rn(o.x, o.y);
        o16[bx + 1] = __floats2half2_rn(o.z, o.w);
    }
}

// ---------------- pooling ----------------
__global__ void k_find_starts(const int* __restrict__ batch) {
    int g = threadIdx.x;
    if (g == GG) { g_start[GG] = NN; return; }
    if (g < GG) {
        int lo = 0, hi = NN;
        while (lo < hi) {
            int mid = (lo + hi) >> 1;
            if (batch[mid] < g) lo = mid + 1; else hi = mid;
        }
        g_start[g] = lo;
    }
}

#define SPLITS 8
__global__ __launch_bounds__(256) void k_pool_partial(const float* __restrict__ emb) {
    int g  = blockIdx.x / SPLITS;
    int sp = blockIdx.x % SPLITS;
    int s0 = g_start[g], s1 = g_start[g + 1];
    int cnt = s1 - s0;
    int per = (cnt + SPLITS - 1) / SPLITS;
    int a = s0 + sp * per;
    int b = min(s1, a + per);
    int t = threadIdx.x;
    float4 acc = make_float4(0.f, 0.f, 0.f, 0.f);
    for (int i = a; i < b; i++) {
        float4 v = ((const float4*)emb)[(size_t)i * HV + t];
        acc.x += v.x; acc.y += v.y; acc.z += v.z; acc.w += v.w;
    }
    float* dstp = &g_pool[g * HH + t * 4];
    atomicAdd(dstp + 0, acc.x);
    atomicAdd(dstp + 1, acc.y);
    atomicAdd(dstp + 2, acc.z);
    atomicAdd(dstp + 3, acc.w);
}

__global__ void k_fin_pool(float* __restrict__ graph_out, float* __restrict__ v0) {
    int g = blockIdx.x;
    int t = threadIdx.x;
    float c = fmaxf((float)(g_start[g + 1] - g_start[g]), 1.0f);
    float invc = 1.0f / c;
    float4 v = ((const float4*)g_pool)[g * HV + t];
    v.x *= invc; v.y *= invc; v.z *= invc; v.w *= invc;
    ((float4*)graph_out)[g * HV + t] = v;
    ((float4*)v0)[g * HV + t] = v;
}

// ---------------- tiny MLP (k-split for parallelism) ----------------
__global__ __launch_bounds__(128) void k_mlp_partial(
    const float* __restrict__ vin, const float* __restrict__ W)
{
    __shared__ __align__(16) float vsT[128 * GG];   // [k][g], 4 KB
    int t  = threadIdx.x;
    int jb = blockIdx.x, ks = blockIdx.y;
    int kbase = ks * 128;
    for (int i = t; i < 128 * GG; i += 128) {
        int k = i >> 3, g = i & 7;
        vsT[i] = vin[g * HH + kbase + k];
    }
    __syncthreads();
    int j = jb * 128 + t;
    float acc[GG] = {};
    #pragma unroll 16
    for (int k = 0; k < 128; k++) {
        float w = W[(size_t)(kbase + k) * HH + j];
        float4 a0 = *(const float4*)&vsT[k * 8];
        float4 a1 = *(const float4*)&vsT[k * 8 + 4];
        acc[0] += a0.x * w; acc[1] += a0.y * w; acc[2] += a0.z * w; acc[3] += a0.w * w;
        acc[4] += a1.x * w; acc[5] += a1.y * w; acc[6] += a1.z * w; acc[7] += a1.w * w;
    }
    #pragma unroll
    for (int g = 0; g < GG; g++)
        g_mpart[ks][g * HH + j] = acc[g];
}

__global__ __launch_bounds__(256) void k_mlp_fin(
    const float* __restrict__ b, float* __restrict__ vout)
{
    int i = blockIdx.x * blockDim.x + threadIdx.x;   // over GG*HH
    int j = i & (HH - 1);
    float s = 0.f;
    #pragma unroll
    for (int ks = 0; ks < 8; ks++) s += g_mpart[ks][i];
    vout[i] = fmaxf(s + b[j], 0.f);
}

__global__ __launch_bounds__(256) void k_head(
    const float* __restrict__ v, const float* __restrict__ wo,
    const float* __restrict__ bo, float* __restrict__ sv)
{
    __shared__ float sm[8];
    int t = threadIdx.x;
    float4 w4 = ((const float4*)wo)[t];
    for (int g = 0; g < GG; g++) {
        float4 x = ((const float4*)v)[g * HV + t];
        float s = x.x * w4.x + x.y * w4.y + x.z * w4.z + x.w * w4.w;
        float tot = block_sum256(s, sm);
        if (t == 0) sv[g] = tot + bo[0];
    }
}

// ---------------- launch ----------------
extern "C" void kernel_launch(void* const* d_in, const int* in_sizes, int n_in,
                              void* d_out, int out_size) {
    const float* x     = (const float*)d_in[0];
    const int*   ei    = (const int*)  d_in[1];
    const int*   batch = (const int*)  d_in[2];
    const float* W1    = (const float*)d_in[3];
    const float* b1    = (const float*)d_in[4];
    const float* Wh    = (const float*)d_in[5];
    const float* bh    = (const float*)d_in[6];
    const float* lng   = (const float*)d_in[7];
    const float* lnb   = (const float*)d_in[8];
    const float* vW    = (const float*)d_in[9];
    const float* vb    = (const float*)d_in[10];
    const float* vWo   = (const float*)d_in[11];
    const float* vbo   = (const float*)d_in[12];

    const int* src = ei;
    const int* dst = ei + EE;

    float* node_out  = (float*)d_out;
    float* graph_out = node_out + (size_t)NN * HH;
    float* sv_out    = graph_out + GG * HH;

    // resolve true DEVICE addresses of __device__ symbols (ATS pitfall!)
    float *x1, *h, *dinv, *vbuf, *poolp;
    __half *hw, *a16, *x16, *wt, *w1t;
    int   *cntp;
    cudaGetSymbolAddress((void**)&hw,    g_hw);
    cudaGetSymbolAddress((void**)&x1,    g_x1);
    cudaGetSymbolAddress((void**)&h,     g_h);
    cudaGetSymbolAddress((void**)&dinv,  g_dinv);
    cudaGetSymbolAddress((void**)&vbuf,  g_vbuf);
    cudaGetSymbolAddress((void**)&poolp, g_pool);
    cudaGetSymbolAddress((void**)&cntp,  g_cnt);
    cudaGetSymbolAddress((void**)&a16,   g_a16);
    cudaGetSymbolAddress((void**)&x16,   g_x16);
    cudaGetSymbolAddress((void**)&wt,    g_wt);
    cudaGetSymbolAddress((void**)&w1t,   g_w1t);
    float* vbuf0 = vbuf;
    float* vbuf1 = vbuf + GG * HH;

    cudaFuncSetAttribute(k_tgemm, cudaFuncAttributeMaxDynamicSharedMemorySize, SM_TOTAL);

    dim3 tg(HH / GBN, (NN + GBM - 1) / GBM);   // (8, 79)

    // memset nodes (not kernel launches) — zero degree counters and pool buffer
    cudaMemsetAsync(cntp,  0, NN * sizeof(int));
    cudaMemsetAsync(poolp, 0, GG * HH * sizeof(float));

    // ---- kernel launches 1-3, then layer-1 GEMM as launch #4 (ncu window) ----
    k_prep1<<<XSPLIT_BLOCKS + 128, 256>>>(x, W1);                            // 1
    k_count_deg<<<(EE + 255) / 256, 256>>>(dst);                             // 2
    k_fin_dinv<<<(NN + 255) / 256, 256>>>();                                 // 3
    k_tgemm<<<tg, 256, SM_TOTAL>>>(x16, w1t, hw, dinv, NN, DIN);             // 4

    // ---- rest of CSR + weight prep (overlap region) ----
    k_scan_off<<<1, 1024>>>();
    k_fill_csr<<<(EE + 255) / 256, 256>>>(src, dst);
    for (int l = 0; l < 3; l++)
        k_wt16<<<dim3(HH / 32, HH / 32), dim3(32, 8)>>>(
            Wh + (size_t)l * HH * HH, wt + (size_t)l * HH * HH, HH, HH);

    // ---- layer 1 agg ----
    k_agg_ln<<<NN, 256>>>((const uint2*)hw, b1, nullptr,
                          lng + 0 * HH, lnb + 0 * HH, h, x1, (__half2*)a16);

    // ---- layer 2 ----
    k_tgemm<<<tg, 256, SM_TOTAL>>>(a16, wt + 0 * (size_t)HH * HH, hw, dinv, NN, HH);
    k_agg_ln<<<NN, 256>>>((const uint2*)hw, bh + 0 * HH, x1,
                          lng + 1 * HH, lnb + 1 * HH, h, nullptr, (__half2*)a16);

    // ---- layer 3 ----
    k_tgemm<<<tg, 256, SM_TOTAL>>>(a16, wt + 1 * (size_t)HH * HH, hw, dinv, NN, HH);
    k_agg_ln<<<NN, 256>>>((const uint2*)hw, bh + 1 * HH, x1,
                          lng + 2 * HH, lnb + 2 * HH, h, nullptr, (__half2*)a16);

    // ---- layer 4 ----
    k_tgemm<<<tg, 256, SM_TOTAL>>>(a16, wt + 2 * (size_t)HH * HH, hw, dinv, NN, HH);
    k_agg_ln<<<NN, 256>>>((const uint2*)hw, bh + 2 * HH, h,
                          lng + 3 * HH, lnb + 3 * HH, node_out, nullptr, nullptr);

    // ---- pooling ----
    k_find_starts<<<1, 32>>>(batch);
    k_pool_partial<<<GG * SPLITS, 256>>>(node_out);
    k_fin_pool<<<GG, 256>>>(graph_out, vbuf0);

    // ---- value MLP (6 layers, k-split) + head ----
    for (int i = 0; i < 6; i++) {
        const float* vin = (i & 1) ? vbuf1 : vbuf0;
        float* vout      = (i & 1) ? vbuf0 : vbuf1;
        k_mlp_partial<<<dim3(HH / 128, 8), 128>>>(vin, vW + (size_t)i * HH * HH);
        k_mlp_fin<<<(GG * HH) / 256, 256>>>(vb + i * HH, vout);
    }
    k_head<<<1, 256>>>(vbuf0, vWo, vbo, sv_out);
}

// round 17
// speedup vs baseline: 1.8931x; 1.0153x over previous
#include <cuda_runtime.h>
#include <cuda_bf16.h>
#include <cuda_fp16.h>
#include <cstdint>

#define NN   10000
#define EE   160000
#define DIN  128
#define HH   1024
#define GG   8
#define HV   (HH/4)   // 256 float4 per row
#define EPSL 1e-5f

// ---------------- device scratch (static; no allocation allowed) ----------------
__device__ float g_dinv[NN];
__device__ int   g_cnt[NN];
__device__ int   g_off[NN + 1];
__device__ int   g_cur[NN];
__device__ int   g_csr[EE];
__device__ __half g_hw[(size_t)NN * HH]; // (A@W) * dinv[row], fp16 (agg-only operand)
__device__ float g_x1[(size_t)NN * HH];   // saved x1 for residuals (fp32)
__device__ float g_h [(size_t)NN * HH];   // current activation (fp32)
__device__ float g_pool[GG * HH];
__device__ int   g_start[GG + 1];
__device__ float g_vbuf[2][GG * HH];
__device__ float g_mpart[8][GG * HH];     // MLP k-split partials
// fp16 operand buffers for tensor-core GEMMs (plain fp16, single pass)
__device__ __half g_a16[(size_t)NN * HH];      // activations, fp16
__device__ __half g_x16[(size_t)NN * DIN];     // input x, fp16
__device__ __half g_wt[3 * (size_t)HH * HH];   // Wh transposed [N,K], fp16
__device__ __half g_w1t[(size_t)HH * DIN];     // W1 transposed [1024,128], fp16

// ---------------- degree / CSR construction ----------------
__global__ void k_count_deg(const int* __restrict__ dst) {
    int e = blockIdx.x * blockDim.x + threadIdx.x;
    if (e < EE) atomicAdd(&g_cnt[dst[e]], 1);
}

__global__ void k_fin_dinv() {
    int i = blockIdx.x * blockDim.x + threadIdx.x;
    if (i < NN) {
        float deg = (float)(g_cnt[i] + 1);
        g_dinv[i] = rsqrtf(deg);
        g_cur[i]  = 0;
    }
}

__global__ void k_scan_off() {
    __shared__ int partial[1024];
    int t = threadIdx.x;
    int base = t * 10;
    int local[10];
    int s = 0;
    if (t < 1000) {
        #pragma unroll
        for (int j = 0; j < 10; j++) { local[j] = s; s += g_cnt[base + j]; }
    }
    partial[t] = (t < 1000) ? s : 0;
    __syncthreads();
    for (int d = 1; d < 1024; d <<= 1) {
        int v = partial[t];
        int add = (t >= d) ? partial[t - d] : 0;
        __syncthreads();
        partial[t] = v + add;
        __syncthreads();
    }
    int pre = (t > 0) ? partial[t - 1] : 0;
    if (t < 1000) {
        #pragma unroll
        for (int j = 0; j < 10; j++) g_off[base + j] = pre + local[j];
    }
    if (t == 0) g_off[NN] = EE;
}

__global__ void k_fill_csr(const int* __restrict__ src, const int* __restrict__ dst) {
    int e = blockIdx.x * blockDim.x + threadIdx.x;
    if (e < EE) {
        int d = dst[e];
        int p = g_off[d] + atomicAdd(&g_cur[d], 1);
        g_csr[p] = src[e];
    }
}

// ------------- fused prep: x -> fp16 + W1 transpose (one launch) -------------
#define XSPLIT_BLOCKS ((NN * DIN) / 256)               // 5000
__global__ __launch_bounds__(256) void k_prep1(
    const float* __restrict__ x, const float* __restrict__ W1)
{
    int b = blockIdx.x;
    if (b < XSPLIT_BLOCKS) {
        int i = b * 256 + threadIdx.x;
        g_x16[i] = __float2half_rn(x[i]);
    } else {
        __shared__ float tile[32][33];
        int b2 = b - XSPLIT_BLOCKS;                    // 0..127
        int n0 = (b2 & 31) * 32;                       // HH/32 = 32 n-tiles
        int k0 = (b2 >> 5) * 32;                       // DIN/32 = 4 k-tiles
        int tx = threadIdx.x & 31, ty = threadIdx.x >> 5;   // 32 x 8
        #pragma unroll
        for (int i = 0; i < 32; i += 8)
            tile[ty + i][tx] = W1[(size_t)(k0 + ty + i) * HH + n0 + tx];
        __syncthreads();
        #pragma unroll
        for (int i = 0; i < 32; i += 8)
            g_w1t[(size_t)(n0 + ty + i) * DIN + k0 + tx] =
                __float2half_rn(tile[tx][ty + i]);
    }
}

// transpose: W [K,N] fp32 row-major -> T [N,K] fp16
__global__ void k_wt16(const float* __restrict__ W,
                       __half* __restrict__ T, int K, int N) {
    __shared__ float tile[32][33];
    int n0 = blockIdx.x * 32, k0 = blockIdx.y * 32;
    int tx = threadIdx.x, ty = threadIdx.y;       // 32 x 8
    #pragma unroll
    for (int i = 0; i < 32; i += 8)
        tile[ty + i][tx] = W[(size_t)(k0 + ty + i) * N + n0 + tx];
    __syncthreads();
    #pragma unroll
    for (int i = 0; i < 32; i += 8)
        T[(size_t)(n0 + ty + i) * K + k0 + tx] =
            __float2half_rn(tile[tx][ty + i]);
}

// ---------------- tensor-core GEMM via mma.sync (plain fp16, single pass) --------
// C[r,c] = fp16((A @ Wt^T)[r,c] * scale[r]). A fp16 [M,K] row-major,
// Wt fp16 [HH,K] row-major. fp32 accumulators.
#define GBM 128
#define GBN 128
#define TILE_BYTES 16384                           // 128 rows x 128B
#define STAGE_BYTES (2 * TILE_BYTES)               // A + B = 32KB
#define SM_TOTAL    (2 * STAGE_BYTES)              // double buffered = 64KB

__device__ __forceinline__ void stage_load_async(
    const __half* __restrict__ A, const __half* __restrict__ B,
    uint32_t base, int bm, int bn, int k0, int M, int K, int tid)
{
    #pragma unroll
    for (int i = 0; i < 4; i++) {
        int idx = i * 256 + tid;                  // 1024 16B chunks per tile
        int r = idx >> 3, c = idx & 7;
        uint32_t off = (uint32_t)(r * 128 + ((c ^ (r & 7)) * 16));  // XOR swizzle
        int rg = bm + r;
        int pa = (rg < M) ? 16 : 0;
        if (rg >= M) rg = M - 1;                  // clamp pointer, src_size=0 zero-fills
        const void* ga = A + (size_t)rg * K + k0 + c * 8;
        asm volatile("cp.async.cg.shared.global [%0], [%1], 16, %2;"
                     :: "r"(base + off), "l"(ga), "r"(pa) : "memory");
        const void* gb = B + (size_t)(bn + r) * K + k0 + c * 8;
        asm volatile("cp.async.cg.shared.global [%0], [%1], 16;"
                     :: "r"(base + TILE_BYTES + off), "l"(gb) : "memory");
    }
}

__global__ __launch_bounds__(256) void k_tgemm(
    const __half* __restrict__ A, const __half* __restrict__ B,
    __half* __restrict__ C, const float* __restrict__ scale, int M, int K)
{
    extern __shared__ char smem[];
    uint32_t sb = (uint32_t)__cvta_generic_to_shared(smem);
    int tid  = threadIdx.x;
    int lane = tid & 31;
    int wid  = tid >> 5;
    int wm   = (wid >> 2) * 64;                   // warp M offset (0 / 64)
    int wn   = (wid & 3) * 32;                    // warp N offset (0..96)
    int bn = blockIdx.x * GBN, bm = blockIdx.y * GBM;

    float acc[4][4][4];
    #pragma unroll
    for (int a = 0; a < 4; a++)
        #pragma unroll
        for (int b = 0; b < 4; b++)
            #pragma unroll
            for (int c = 0; c < 4; c++) acc[a][b][c] = 0.f;

    const int S = K >> 6;                         // 64-wide K chunks

    // A ldmatrix addressing (x4: rows 0-15 x k-halves)
    int arow = wm + (lane & 15);
    int acol_half = lane >> 4;
    // B ldmatrix addressing (x4: two nt tiles x two k-halves per instruction)
    int brow4 = wn + ((lane >> 4) << 3) + (lane & 7);
    int bcol_half = (lane >> 3) & 1;

    {   // prologue: stage 0
        stage_load_async(A, B, sb, bm, bn, 0, M, K, tid);
        asm volatile("cp.async.commit_group;" ::: "memory");
    }

    for (int s = 0; s < S; s++) {
        if (s + 1 < S) {
            uint32_t base = sb + (uint32_t)((s + 1) & 1) * STAGE_BYTES;
            stage_load_async(A, B, base, bm, bn, (s + 1) << 6, M, K, tid);
            asm volatile("cp.async.commit_group;" ::: "memory");
            asm volatile("cp.async.wait_group 1;" ::: "memory");
        } else {
            asm volatile("cp.async.wait_group 0;" ::: "memory");
        }
        __syncthreads();

        uint32_t aB = sb + (uint32_t)(s & 1) * STAGE_BYTES;
        uint32_t bB = aB + TILE_BYTES;

        #pragma unroll
        for (int ks = 0; ks < 4; ks++) {
            uint32_t af[4][4];
            #pragma unroll
            for (int mt = 0; mt < 4; mt++) {
                int row = arow + mt * 16;
                int c = 2 * ks + acol_half;
                uint32_t off = (uint32_t)(row * 128 + ((c ^ (row & 7)) * 16));
                asm volatile("ldmatrix.sync.aligned.m8n8.x4.shared.b16 {%0,%1,%2,%3}, [%4];"
                             : "=r"(af[mt][0]), "=r"(af[mt][1]),
                               "=r"(af[mt][2]), "=r"(af[mt][3])
                             : "r"(aB + off));
            }
            uint32_t bf[4][2];
            #pragma unroll
            for (int nt2 = 0; nt2 < 2; nt2++) {
                int row = brow4 + nt2 * 16;
                int c = 2 * ks + bcol_half;
                uint32_t off = (uint32_t)(row * 128 + ((c ^ (row & 7)) * 16));
                asm volatile("ldmatrix.sync.aligned.m8n8.x4.shared.b16 {%0,%1,%2,%3}, [%4];"
                             : "=r"(bf[nt2 * 2][0]), "=r"(bf[nt2 * 2][1]),
                               "=r"(bf[nt2 * 2 + 1][0]), "=r"(bf[nt2 * 2 + 1][1])
                             : "r"(bB + off));
            }
            #pragma unroll
            for (int mt = 0; mt < 4; mt++)
                #pragma unroll
                for (int nt = 0; nt < 4; nt++)
                    asm volatile(
                        "mma.sync.aligned.m16n8k16.row.col.f32.f16.f16.f32 "
                        "{%0,%1,%2,%3}, {%4,%5,%6,%7}, {%8,%9}, {%0,%1,%2,%3};"
                        : "+f"(acc[mt][nt][0]), "+f"(acc[mt][nt][1]),
                          "+f"(acc[mt][nt][2]), "+f"(acc[mt][nt][3])
                        : "r"(af[mt][0]), "r"(af[mt][1]), "r"(af[mt][2]), "r"(af[mt][3]),
                          "r"(bf[nt][0]), "r"(bf[nt][1]));
        }
        __syncthreads();
    }

    // epilogue: scale rows by dinv (this IS the dinv[src] factor), store fp16
    int g  = lane >> 2;
    int tq = lane & 3;
    #pragma unroll
    for (int mt = 0; mt < 4; mt++) {
        int r0 = bm + wm + mt * 16 + g;
        int r1 = r0 + 8;
        float s0 = (r0 < M) ? scale[r0] : 0.f;
        float s1 = (r1 < M) ? scale[r1] : 0.f;
        #pragma unroll
        for (int nt = 0; nt < 4; nt++) {
            int col = bn + wn + nt * 8 + tq * 2;
            if (r0 < M) {
                __half2 v = __floats2half2_rn(acc[mt][nt][0] * s0, acc[mt][nt][1] * s0);
                *(__half2*)(C + (size_t)r0 * HH + col) = v;
            }
            if (r1 < M) {
                __half2 v = __floats2half2_rn(acc[mt][nt][2] * s1, acc[mt][nt][3] * s1);
                *(__half2*)(C + (size_t)r1 * HH + col) = v;
            }
        }
    }
}

// ---------------- block reduces ----------------
__device__ __forceinline__ float block_sum256(float v, float* sm) {
    #pragma unroll
    for (int o = 16; o > 0; o >>= 1) v += __shfl_down_sync(0xffffffffu, v, o);
    int w = threadIdx.x >> 5;
    if ((threadIdx.x & 31) == 0) sm[w] = v;
    __syncthreads();
    float r;
    if (threadIdx.x < 8) {
        float x = sm[threadIdx.x];
        #pragma unroll
        for (int o = 4; o > 0; o >>= 1) x += __shfl_down_sync(0xffu, x, o);
        if (threadIdx.x == 0) sm[0] = x;
    }
    __syncthreads();
    r = sm[0];
    __syncthreads();
    return r;
}

__device__ __forceinline__ float block_sum128(float v, float* sm) {
    #pragma unroll
    for (int o = 16; o > 0; o >>= 1) v += __shfl_down_sync(0xffffffffu, v, o);
    int w = threadIdx.x >> 5;
    if ((threadIdx.x & 31) == 0) sm[w] = v;
    __syncthreads();
    float r;
    if (threadIdx.x < 4) {
        float x = sm[threadIdx.x];
        x += __shfl_down_sync(0xFu, x, 2);
        x += __shfl_down_sync(0xFu, x, 1);
        if (threadIdx.x == 0) sm[0] = x;
    }
    __syncthreads();
    r = sm[0];
    __syncthreads();
    return r;
}

__device__ __forceinline__ void acc_u4(float* acc, uint4 raw) {
    float2 f0 = __half22float2(*(__half2*)&raw.x);
    float2 f1 = __half22float2(*(__half2*)&raw.y);
    float2 f2 = __half22float2(*(__half2*)&raw.z);
    float2 f3 = __half22float2(*(__half2*)&raw.w);
    acc[0] += f0.x; acc[1] += f0.y; acc[2] += f1.x; acc[3] += f1.y;
    acc[4] += f2.x; acc[5] += f2.y; acc[6] += f3.x; acc[7] += f3.y;
}

// ---- fused: gather-sum(CSR, fp16 rows pre-scaled by dinv) + bias + res + LN + ReLU ----
// 128 threads per node row; thread t owns uint4 #t (8 fp16 values).
// Edge indices read directly (L1-broadcast), no smem staging, no in-loop barriers.
__global__ __launch_bounds__(128) void k_agg_ln(
    const uint4* __restrict__ hw,
    const float* __restrict__ bias,
    const float* __restrict__ res,            // nullable
    const float* __restrict__ gamma,
    const float* __restrict__ beta,
    float* __restrict__ out,
    float* __restrict__ save_pre,             // nullable
    __half2* __restrict__ o16)                // nullable: fp16 copy of out (GEMM A)
{
    __shared__ float sm[4];
    int i = blockIdx.x;
    int t = threadIdx.x;

    float acc[8] = {};
    acc_u4(acc, hw[(size_t)i * 128 + t]);         // self loop (pre-scaled)

    int e0 = g_off[i], e1 = g_off[i + 1];
    int e = e0;
    for (; e + 8 <= e1; e += 8) {
        int i0 = g_csr[e];     int i1 = g_csr[e + 1];
        int i2 = g_csr[e + 2]; int i3 = g_csr[e + 3];
        int i4 = g_csr[e + 4]; int i5 = g_csr[e + 5];
        int i6 = g_csr[e + 6]; int i7 = g_csr[e + 7];
        uint4 v0 = hw[(size_t)i0 * 128 + t];
        uint4 v1 = hw[(size_t)i1 * 128 + t];
        uint4 v2 = hw[(size_t)i2 * 128 + t];
        uint4 v3 = hw[(size_t)i3 * 128 + t];
        uint4 v4 = hw[(size_t)i4 * 128 + t];
        uint4 v5 = hw[(size_t)i5 * 128 + t];
        uint4 v6 = hw[(size_t)i6 * 128 + t];
        uint4 v7 = hw[(size_t)i7 * 128 + t];
        acc_u4(acc, v0); acc_u4(acc, v1); acc_u4(acc, v2); acc_u4(acc, v3);
        acc_u4(acc, v4); acc_u4(acc, v5); acc_u4(acc, v6); acc_u4(acc, v7);
    }
    for (; e < e1; e++)
        acc_u4(acc, hw[(size_t)g_csr[e] * 128 + t]);

    float di = g_dinv[i];
    float4 b0 = ((const float4*)bias)[2 * t];
    float4 b1 = ((const float4*)bias)[2 * t + 1];
    float y[8];
    y[0] = acc[0] * di + b0.x; y[1] = acc[1] * di + b0.y;
    y[2] = acc[2] * di + b0.z; y[3] = acc[3] * di + b0.w;
    y[4] = acc[4] * di + b1.x; y[5] = acc[5] * di + b1.y;
    y[6] = acc[6] * di + b1.z; y[7] = acc[7] * di + b1.w;
    if (res) {
        float4 r0 = ((const float4*)res)[(size_t)i * HV + 2 * t];
        float4 r1 = ((const float4*)res)[(size_t)i * HV + 2 * t + 1];
        y[0] += r0.x; y[1] += r0.y; y[2] += r0.z; y[3] += r0.w;
        y[4] += r1.x; y[5] += r1.y; y[6] += r1.z; y[7] += r1.w;
    }
    if (save_pre) {
        ((float4*)save_pre)[(size_t)i * HV + 2 * t] =
            make_float4(y[0], y[1], y[2], y[3]);
        ((float4*)save_pre)[(size_t)i * HV + 2 * t + 1] =
            make_float4(y[4], y[5], y[6], y[7]);
    }

    float s = y[0] + y[1] + y[2] + y[3] + y[4] + y[5] + y[6] + y[7];
    float mean = block_sum128(s, sm) * (1.0f / HH);
    float d[8], sq = 0.f;
    #pragma unroll
    for (int j = 0; j < 8; j++) { d[j] = y[j] - mean; sq += d[j] * d[j]; }
    float var = block_sum128(sq, sm) * (1.0f / HH);
    float inv = rsqrtf(var + EPSL);

    float4 g0 = ((const float4*)gamma)[2 * t];
    float4 g1 = ((const float4*)gamma)[2 * t + 1];
    float4 e0v = ((const float4*)beta)[2 * t];
    float4 e1v = ((const float4*)beta)[2 * t + 1];
    float o[8];
    o[0] = fmaxf(d[0] * inv * g0.x + e0v.x, 0.f);
    o[1] = fmaxf(d[1] * inv * g0.y + e0v.y, 0.f);
    o[2] = fmaxf(d[2] * inv * g0.z + e0v.z, 0.f);
    o[3] = fmaxf(d[3] * inv * g0.w + e0v.w, 0.f);
    o[4] = fmaxf(d[4] * inv * g1.x + e1v.x, 0.f);
    o[5] = fmaxf(d[5] * inv * g1.y + e1v.y, 0.f);
    o[6] = fmaxf(d[6] * inv * g1.z + e1v.z, 0.f);
    o[7] = fmaxf(d[7] * inv * g1.w + e1v.w, 0.f);
    ((float4*)out)[(size_t)i * HV + 2 * t]     = make_float4(o[0], o[1], o[2], o[3]);
    ((float4*)out)[(size_t)i * HV + 2 * t + 1] = make_float4(o[4], o[5], o[6], o[7]);

    if (o16) {
        size_t bx = (size_t)i * (HH / 2) + t * 4;
        o16[bx]     = __floats2half2_rn(o[0], o[1]);
        o16[bx + 1] = __floats2half2_rn(o[2], o[3]);
        o16[bx + 2] = __floats2half2_rn(o[4], o[5]);
        o16[bx + 3] = __floats2half2_rn(o[6], o[7]);
    }
}

// ---------------- pooling ----------------
__global__ void k_find_starts(const int* __restrict__ batch) {
    int g = threadIdx.x;
    if (g == GG) { g_start[GG] = NN; return; }
    if (g < GG) {
        int lo = 0, hi = NN;
        while (lo < hi) {
            int mid = (lo + hi) >> 1;
            if (batch[mid] < g) lo = mid + 1; else hi = mid;
        }
        g_start[g] = lo;
    }
}

#define SPLITS 8
__global__ __launch_bounds__(256) void k_pool_partial(const float* __restrict__ emb) {
    int g  = blockIdx.x / SPLITS;
    int sp = blockIdx.x % SPLITS;
    int s0 = g_start[g], s1 = g_start[g + 1];
    int cnt = s1 - s0;
    int per = (cnt + SPLITS - 1) / SPLITS;
    int a = s0 + sp * per;
    int b = min(s1, a + per);
    int t = threadIdx.x;
    float4 acc = make_float4(0.f, 0.f, 0.f, 0.f);
    for (int i = a; i < b; i++) {
        float4 v = ((const float4*)emb)[(size_t)i * HV + t];
        acc.x += v.x; acc.y += v.y; acc.z += v.z; acc.w += v.w;
    }
    float* dstp = &g_pool[g * HH + t * 4];
    atomicAdd(dstp + 0, acc.x);
    atomicAdd(dstp + 1, acc.y);
    atomicAdd(dstp + 2, acc.z);
    atomicAdd(dstp + 3, acc.w);
}

__global__ void k_fin_pool(float* __restrict__ graph_out, float* __restrict__ v0) {
    int g = blockIdx.x;
    int t = threadIdx.x;
    float c = fmaxf((float)(g_start[g + 1] - g_start[g]), 1.0f);
    float invc = 1.0f / c;
    float4 v = ((const float4*)g_pool)[g * HV + t];
    v.x *= invc; v.y *= invc; v.z *= invc; v.w *= invc;
    ((float4*)graph_out)[g * HV + t] = v;
    ((float4*)v0)[g * HV + t] = v;
}

// ---------------- tiny MLP (k-split for parallelism) ----------------
__global__ __launch_bounds__(128) void k_mlp_partial(
    const float* __restrict__ vin, const float* __restrict__ W)
{
    __shared__ __align__(16) float vsT[128 * GG];   // [k][g], 4 KB
    int t  = threadIdx.x;
    int jb = blockIdx.x, ks = blockIdx.y;
    int kbase = ks * 128;
    for (int i = t; i < 128 * GG; i += 128) {
        int k = i >> 3, g = i & 7;
        vsT[i] = vin[g * HH + kbase + k];
    }
    __syncthreads();
    int j = jb * 128 + t;
    float acc[GG] = {};
    #pragma unroll 16
    for (int k = 0; k < 128; k++) {
        float w = W[(size_t)(kbase + k) * HH + j];
        float4 a0 = *(const float4*)&vsT[k * 8];
        float4 a1 = *(const float4*)&vsT[k * 8 + 4];
        acc[0] += a0.x * w; acc[1] += a0.y * w; acc[2] += a0.z * w; acc[3] += a0.w * w;
        acc[4] += a1.x * w; acc[5] += a1.y * w; acc[6] += a1.z * w; acc[7] += a1.w * w;
    }
    #pragma unroll
    for (int g = 0; g < GG; g++)
        g_mpart[ks][g * HH + j] = acc[g];
}

__global__ __launch_bounds__(256) void k_mlp_fin(
    const float* __restrict__ b, float* __restrict__ vout)
{
    int i = blockIdx.x * blockDim.x + threadIdx.x;   // over GG*HH
    int j = i & (HH - 1);
    float s = 0.f;
    #pragma unroll
    for (int ks = 0; ks < 8; ks++) s += g_mpart[ks][i];
    vout[i] = fmaxf(s + b[j], 0.f);
}

__global__ __launch_bounds__(256) void k_head(
    const float* __restrict__ v, const float* __restrict__ wo,
    const float* __restrict__ bo, float* __restrict__ sv)
{
    __shared__ float sm[8];
    int t = threadIdx.x;
    float4 w4 = ((const float4*)wo)[t];
    for (int g = 0; g < GG; g++) {
        float4 x = ((const float4*)v)[g * HV + t];
        float s = x.x * w4.x + x.y * w4.y + x.z * w4.z + x.w * w4.w;
        float tot = block_sum256(s, sm);
        if (t == 0) sv[g] = tot + bo[0];
    }
}

// ---------------- launch ----------------
extern "C" void kernel_launch(void* const* d_in, const int* in_sizes, int n_in,
                              void* d_out, int out_size) {
    const float* x     = (const float*)d_in[0];
    const int*   ei    = (const int*)  d_in[1];
    const int*   batch = (const int*)  d_in[2];
    const float* W1    = (const float*)d_in[3];
    const float* b1    = (const float*)d_in[4];
    const float* Wh    = (const float*)d_in[5];
    const float* bh    = (const float*)d_in[6];
    const float* lng   = (const float*)d_in[7];
    const float* lnb   = (const float*)d_in[8];
    const float* vW    = (const float*)d_in[9];
    const float* vb    = (const float*)d_in[10];
    const float* vWo   = (const float*)d_in[11];
    const float* vbo   = (const float*)d_in[12];

    const int* src = ei;
    const int* dst = ei + EE;

    float* node_out  = (float*)d_out;
    float* graph_out = node_out + (size_t)NN * HH;
    float* sv_out    = graph_out + GG * HH;

    // resolve true DEVICE addresses of __device__ symbols (ATS pitfall!)
    float *x1, *h, *dinv, *vbuf, *poolp;
    __half *hw, *a16, *x16, *wt, *w1t;
    int   *cntp;
    cudaGetSymbolAddress((void**)&hw,    g_hw);
    cudaGetSymbolAddress((void**)&x1,    g_x1);
    cudaGetSymbolAddress((void**)&h,     g_h);
    cudaGetSymbolAddress((void**)&dinv,  g_dinv);
    cudaGetSymbolAddress((void**)&vbuf,  g_vbuf);
    cudaGetSymbolAddress((void**)&poolp, g_pool);
    cudaGetSymbolAddress((void**)&cntp,  g_cnt);
    cudaGetSymbolAddress((void**)&a16,   g_a16);
    cudaGetSymbolAddress((void**)&x16,   g_x16);
    cudaGetSymbolAddress((void**)&wt,    g_wt);
    cudaGetSymbolAddress((void**)&w1t,   g_w1t);
    float* vbuf0 = vbuf;
    float* vbuf1 = vbuf + GG * HH;

    cudaFuncSetAttribute(k_tgemm, cudaFuncAttributeMaxDynamicSharedMemorySize, SM_TOTAL);

    dim3 tg(HH / GBN, (NN + GBM - 1) / GBM);   // (8, 79)

    // memset nodes (not kernel launches) — zero degree counters and pool buffer
    cudaMemsetAsync(cntp,  0, NN * sizeof(int));
    cudaMemsetAsync(poolp, 0, GG * HH * sizeof(float));

    // ---- kernel launches 1-3, then layer-1 GEMM as launch #4 (ncu window) ----
    k_prep1<<<XSPLIT_BLOCKS + 128, 256>>>(x, W1);                            // 1
    k_count_deg<<<(EE + 255) / 256, 256>>>(dst);                             // 2
    k_fin_dinv<<<(NN + 255) / 256, 256>>>();                                 // 3
    k_tgemm<<<tg, 256, SM_TOTAL>>>(x16, w1t, hw, dinv, NN, DIN);             // 4

    // ---- rest of CSR + weight prep (overlap region) ----
    k_scan_off<<<1, 1024>>>();
    k_fill_csr<<<(EE + 255) / 256, 256>>>(src, dst);
    for (int l = 0; l < 3; l++)
        k_wt16<<<dim3(HH / 32, HH / 32), dim3(32, 8)>>>(
            Wh + (size_t)l * HH * HH, wt + (size_t)l * HH * HH, HH, HH);

    // ---- layer 1 agg ----
    k_agg_ln<<<NN, 128>>>((const uint4*)hw, b1, nullptr,
                          lng + 0 * HH, lnb + 0 * HH, h, x1, (__half2*)a16);

    // ---- layer 2 ----
    k_tgemm<<<tg, 256, SM_TOTAL>>>(a16, wt + 0 * (size_t)HH * HH, hw, dinv, NN, HH);
    k_agg_ln<<<NN, 128>>>((const uint4*)hw, bh + 0 * HH, x1,
                          lng + 1 * HH, lnb + 1 * HH, h, nullptr, (__half2*)a16);

    // ---- layer 3 ----
    k_tgemm<<<tg, 256, SM_TOTAL>>>(a16, wt + 1 * (size_t)HH * HH, hw, dinv, NN, HH);
    k_agg_ln<<<NN, 128>>>((const uint4*)hw, bh + 1 * HH, x1,
                          lng + 2 * HH, lnb + 2 * HH, h, nullptr, (__half2*)a16);

    // ---- layer 4 ----
    k_tgemm<<<tg, 256, SM_TOTAL>>>(a16, wt + 2 * (size_t)HH * HH, hw, dinv, NN, HH);
    k_agg_ln<<<NN, 128>>>((const uint4*)hw, bh + 2 * HH, h,
                          lng + 3 * HH, lnb + 3 * HH, node_out, nullptr, nullptr);

    // ---- pooling ----
    k_find_starts<<<1, 32>>>(batch);
    k_pool_partial<<<GG * SPLITS, 256>>>(node_out);
    k_fin_pool<<<GG, 256>>>(graph_out, vbuf0);

    // ---- value MLP (6 layers, k-split) + head ----
    for (int i = 0; i < 6; i++) {
        const float* vin = (i & 1) ? vbuf1 : vbuf0;
        float* vout      = (i & 1) ? vbuf0 : vbuf1;
        k_mlp_partial<<<dim3(HH / 128, 8), 128>>>(vin, vW + (size_t)i * HH * HH);
        k_mlp_fin<<<(GG * HH) / 256, 256>>>(vb + i * HH, vout);
    }
    k_head<<<1, 256>>>(vbuf0, vWo, vbo, sv_out);
}